// round 1
// baseline (speedup 1.0000x reference)
#include <cuda_runtime.h>

#define NN 50000
#define EE 600000
#define HIDD 128
#define NH 8
#define DDIM 16

// ---------------- scratch (device globals; no allocation allowed) ----------------
__device__ float g_Qh[(size_t)NN * HIDD];
__device__ float g_Kh[(size_t)NN * HIDD];
__device__ float g_Vh[(size_t)NN * HIDD];
__device__ float g_Eh[(size_t)EE * 256];   // [Ew | Eb] per edge
__device__ float g_ce[(size_t)EE * HIDD];  // conn_e / e_attn
__device__ float g_ssum[(size_t)NN * NH];
__device__ float g_agg[(size_t)NN * HIDD];
__device__ float g_row[(size_t)NN * HIDD];
__device__ float g_hpre[(size_t)NN * HIDD];
__device__ float g_h1[(size_t)NN * HIDD];
__device__ float g_mlp[(size_t)NN * 256];

// ---------------- generic SGEMM: C[M, ldw-sliced 128 cols] = A[M,KD] @ W[KD,ldw] ----------------
// EPI 0: C = acc (+bias if bias!=null)
// EPI 1: C = relu(acc + bias)
// EPI 2: C = LayerNorm(resid + acc + bias) * g + b   (requires full-row tile: grid.y==1, ldc==128)
template <int KD, int EPI>
__global__ void __launch_bounds__(256) sgemm_k(
    const float* __restrict__ A, const float* __restrict__ W, int ldw,
    const float* __restrict__ bias, const float* __restrict__ resid,
    const float* __restrict__ lng, const float* __restrict__ lnb,
    float* __restrict__ C, int ldc, int M)
{
    __shared__ float As[16][132];   // padded: 132 % 32 == 4 -> reduced store conflicts
    __shared__ float Ws[16][128];

    const int t = threadIdx.x;
    const int m0 = blockIdx.x * 128;
    const int n0 = blockIdx.y * 128;
    const int tx = t & 15, ty = t >> 4;

    float acc[8][8];
#pragma unroll
    for (int i = 0; i < 8; i++)
#pragma unroll
        for (int j = 0; j < 8; j++) acc[i][j] = 0.f;

    const int arow = t >> 2;          // 0..63
    const int acol = (t & 3) * 4;     // 0,4,8,12
    const int wrow = t >> 5;          // 0..7
    const int wcol = (t & 31) * 4;    // 0..124

    for (int kt = 0; kt < KD; kt += 16) {
#pragma unroll
        for (int p = 0; p < 2; p++) {
            int r = arow + p * 64;
            float4 v = make_float4(0.f, 0.f, 0.f, 0.f);
            if (m0 + r < M) v = *(const float4*)&A[(size_t)(m0 + r) * KD + kt + acol];
            As[acol + 0][r] = v.x; As[acol + 1][r] = v.y;
            As[acol + 2][r] = v.z; As[acol + 3][r] = v.w;
        }
#pragma unroll
        for (int p = 0; p < 2; p++) {
            int kr = wrow + p * 8;
            *(float4*)&Ws[kr][wcol] = *(const float4*)&W[(size_t)(kt + kr) * ldw + n0 + wcol];
        }
        __syncthreads();
#pragma unroll
        for (int k = 0; k < 16; k++) {
            float a[8], b[8];
            *(float4*)&a[0] = *(const float4*)&As[k][ty * 8];
            *(float4*)&a[4] = *(const float4*)&As[k][ty * 8 + 4];
            *(float4*)&b[0] = *(const float4*)&Ws[k][tx * 8];
            *(float4*)&b[4] = *(const float4*)&Ws[k][tx * 8 + 4];
#pragma unroll
            for (int i = 0; i < 8; i++)
#pragma unroll
                for (int j = 0; j < 8; j++) acc[i][j] = fmaf(a[i], b[j], acc[i][j]);
        }
        __syncthreads();
    }

    if (EPI == 0 || EPI == 1) {
#pragma unroll
        for (int i = 0; i < 8; i++) {
            int r = m0 + ty * 8 + i;
            if (r >= M) continue;
            float v[8];
#pragma unroll
            for (int j = 0; j < 8; j++) {
                float x = acc[i][j];
                if (bias) x += bias[n0 + tx * 8 + j];
                if (EPI == 1) x = fmaxf(x, 0.f);
                v[j] = x;
            }
            *(float4*)&C[(size_t)r * ldc + n0 + tx * 8] = make_float4(v[0], v[1], v[2], v[3]);
            *(float4*)&C[(size_t)r * ldc + n0 + tx * 8 + 4] = make_float4(v[4], v[5], v[6], v[7]);
        }
    } else {
        // EPI 2: LayerNorm. Row r is owned by the 16 tx-threads of one ty group,
        // which are a contiguous half-warp -> shuffle reduction.
#pragma unroll
        for (int i = 0; i < 8; i++) {
            int r = m0 + ty * 8 + i;
            bool ok = (r < M);
            float v[8];
            float s = 0.f, s2 = 0.f;
#pragma unroll
            for (int j = 0; j < 8; j++) {
                int c = tx * 8 + j;
                float x = acc[i][j] + bias[c];
                if (ok) x += resid[(size_t)r * 128 + c];
                v[j] = x;
                s += x;
                s2 += x * x;
            }
#pragma unroll
            for (int off = 1; off < 16; off <<= 1) {
                s += __shfl_xor_sync(0xffffffffu, s, off);
                s2 += __shfl_xor_sync(0xffffffffu, s2, off);
            }
            float mean = s * (1.f / 128.f);
            float var = s2 * (1.f / 128.f) - mean * mean;
            float rstd = rsqrtf(var + 1e-5f);
            if (ok) {
                float o[8];
#pragma unroll
                for (int j = 0; j < 8; j++) {
                    int c = tx * 8 + j;
                    o[j] = (v[j] - mean) * rstd * lng[c] + lnb[c];
                }
                *(float4*)&C[(size_t)r * 128 + tx * 8] = make_float4(o[0], o[1], o[2], o[3]);
                *(float4*)&C[(size_t)r * 128 + tx * 8 + 4] = make_float4(o[4], o[5], o[6], o[7]);
            }
        }
    }
}

// ---------------- edge pass: conn_e, scores, segment accumulation ----------------
// one warp per edge. Softmax max-shift dropped (scores clipped to +-5 -> exact).
__global__ void __launch_bounds__(256) edge_kernel(const int* __restrict__ ei,
                                                   const float* __restrict__ Aw)
{
    int e = (int)((blockIdx.x * (size_t)blockDim.x + threadIdx.x) >> 5);
    int l = threadIdx.x & 31;
    if (e >= EE) return;
    int dst = ei[e];
    int src = ei[EE + e];
    int c0 = l * 4;
    int h = l >> 2;
    int dbase = (l & 3) * 4;

    float4 q = *(const float4*)&g_Qh[(size_t)dst * HIDD + c0];
    float4 kk = *(const float4*)&g_Kh[(size_t)src * HIDD + c0];
    float4 ew = *(const float4*)&g_Eh[(size_t)e * 256 + c0];
    float4 eb = *(const float4*)&g_Eh[(size_t)e * 256 + 128 + c0];
    float4 vv = *(const float4*)&g_Vh[(size_t)src * HIDD + c0];

    const float* qf = (const float*)&q;
    const float* kf = (const float*)&kk;
    const float* ewf = (const float*)&ew;
    const float* ebf = (const float*)&eb;
    const float* vf = (const float*)&vv;

    float ce[4];
    float part = 0.f;
#pragma unroll
    for (int i = 0; i < 4; i++) {
        float m = qf[i] + kf[i];
        float cc = m * ewf[i];
        float ss = sqrtf(fabsf(cc));
        ss = (cc >= 0.f) ? ss : -ss;          // signed sqrt
        float val = ss + ebf[i];
        ce[i] = fmaxf(val, 0.f);
        part += ce[i] * Aw[(dbase + i) * NH + h];
    }
    *(float4*)&g_ce[(size_t)e * HIDD + c0] = make_float4(ce[0], ce[1], ce[2], ce[3]);

    part += __shfl_xor_sync(0xffffffffu, part, 1);
    part += __shfl_xor_sync(0xffffffffu, part, 2);
    float s = fminf(fmaxf(part, -5.f), 5.f);
    float p = __expf(s);   // |rel err| of __expf ~1e-6 over [-5,5]: fine

    if ((l & 3) == 0) atomicAdd(&g_ssum[(size_t)dst * NH + h], p);
#pragma unroll
    for (int i = 0; i < 4; i++) {
        atomicAdd(&g_agg[(size_t)dst * HIDD + c0 + i], vf[i] * p);
        atomicAdd(&g_row[(size_t)dst * HIDD + c0 + i], ce[i] * p);
    }
}

// ---------------- node pass: normalize, rowV = row @ Bw, deg scaling ----------------
__global__ void __launch_bounds__(256) node_kernel(const float* __restrict__ Bw,
                                                   const float* __restrict__ deg_coef,
                                                   const float* __restrict__ log_deg)
{
    __shared__ float rbuf[8][HIDD];
    int n = (int)((blockIdx.x * (size_t)blockDim.x + threadIdx.x) >> 5);
    int wl = (threadIdx.x >> 5) & 7;
    int l = threadIdx.x & 31;
    if (n >= NN) return;
    int h = l >> 2;
    int c0 = l * 4;

    float rs = 1.f / (g_ssum[(size_t)n * NH + h] + 1e-16f);
    float4 a = *(const float4*)&g_agg[(size_t)n * HIDD + c0];
    float4 r = *(const float4*)&g_row[(size_t)n * HIDD + c0];
    a.x *= rs; a.y *= rs; a.z *= rs; a.w *= rs;
    r.x *= rs; r.y *= rs; r.z *= rs; r.w *= rs;
    *(float4*)&rbuf[wl][c0] = r;
    __syncwarp();

    float4 q = *(const float4*)&g_Qh[(size_t)n * HIDD + c0];
    const float* af = (const float*)&a;
    const float* qf = (const float*)&q;
    float ld = log_deg[n];

    float out[4];
#pragma unroll
    for (int i = 0; i < 4; i++) {
        int c = c0 + i;
        float rv = 0.f;
#pragma unroll
        for (int d = 0; d < DDIM; d++)
            rv = fmaf(rbuf[wl][h * DDIM + d], __ldg(&Bw[d * HIDD + c]), rv);
        float ha = qf[i] + af[i] + rv;
        out[i] = ha * (deg_coef[2 * c] + ld * deg_coef[2 * c + 1]);
    }
    *(float4*)&g_hpre[(size_t)n * HIDD + c0] = make_float4(out[0], out[1], out[2], out[3]);
}

// ---------------- launch ----------------
extern "C" void kernel_launch(void* const* d_in, const int* in_sizes, int n_in,
                              void* d_out, int out_size)
{
    const float* x        = (const float*)d_in[0];
    const float* conn     = (const float*)d_in[1];
    const float* log_deg  = (const float*)d_in[2];
    const int*   ei       = (const int*)d_in[3];
    const float* WQ       = (const float*)d_in[4];
    const float* WK       = (const float*)d_in[5];
    const float* WV       = (const float*)d_in[6];
    const float* WE       = (const float*)d_in[7];
    const float* Aw       = (const float*)d_in[8];
    const float* Bw       = (const float*)d_in[9];
    const float* Ho_w     = (const float*)d_in[10];
    const float* Ho_b     = (const float*)d_in[11];
    const float* Eo_w     = (const float*)d_in[12];
    const float* Eo_b     = (const float*)d_in[13];
    const float* deg_coef = (const float*)d_in[14];
    const float* ln1h_g   = (const float*)d_in[15];
    const float* ln1h_b   = (const float*)d_in[16];
    const float* ln1e_g   = (const float*)d_in[17];
    const float* ln1e_b   = (const float*)d_in[18];
    const float* ln2h_g   = (const float*)d_in[19];
    const float* ln2h_b   = (const float*)d_in[20];
    const float* W1       = (const float*)d_in[21];
    const float* b1       = (const float*)d_in[22];
    const float* W2       = (const float*)d_in[23];
    const float* b2       = (const float*)d_in[24];

    float* out_h = (float*)d_out;
    float* out_e = out_h + (size_t)NN * HIDD;

    float *Qh, *Kh, *Vh, *Eh, *ce, *ssum, *agg, *row, *hpre, *h1, *mlp;
    cudaGetSymbolAddress((void**)&Qh, g_Qh);
    cudaGetSymbolAddress((void**)&Kh, g_Kh);
    cudaGetSymbolAddress((void**)&Vh, g_Vh);
    cudaGetSymbolAddress((void**)&Eh, g_Eh);
    cudaGetSymbolAddress((void**)&ce, g_ce);
    cudaGetSymbolAddress((void**)&ssum, g_ssum);
    cudaGetSymbolAddress((void**)&agg, g_agg);
    cudaGetSymbolAddress((void**)&row, g_row);
    cudaGetSymbolAddress((void**)&hpre, g_hpre);
    cudaGetSymbolAddress((void**)&h1, g_h1);
    cudaGetSymbolAddress((void**)&mlp, g_mlp);

    const int gN = (NN + 127) / 128;   // 391
    const int gE = (EE + 127) / 128;   // 4688

    // zero accumulators (graph replays must be deterministic)
    cudaMemsetAsync(ssum, 0, (size_t)NN * NH * sizeof(float), 0);
    cudaMemsetAsync(agg, 0, (size_t)NN * HIDD * sizeof(float), 0);
    cudaMemsetAsync(row, 0, (size_t)NN * HIDD * sizeof(float), 0);

    // Qh, Kh, Vh
    sgemm_k<128, 0><<<dim3(gN, 1), 256>>>(x, WQ, 128, nullptr, nullptr, nullptr, nullptr, Qh, 128, NN);
    sgemm_k<128, 0><<<dim3(gN, 1), 256>>>(x, WK, 128, nullptr, nullptr, nullptr, nullptr, Kh, 128, NN);
    sgemm_k<128, 0><<<dim3(gN, 1), 256>>>(x, WV, 128, nullptr, nullptr, nullptr, nullptr, Vh, 128, NN);
    // Eh = conn @ WE  [E,256]
    sgemm_k<128, 0><<<dim3(gE, 2), 256>>>(conn, WE, 256, nullptr, nullptr, nullptr, nullptr, Eh, 256, EE);

    // edge pass (conn_e + softmax-weighted segment sums)
    edge_kernel<<<(EE * 32 + 255) / 256, 256>>>(ei, Aw);
    // node pass -> h_pre
    node_kernel<<<(NN * 32 + 255) / 256, 256>>>(Bw, deg_coef, log_deg);

    // h1 = LN1h(x + hpre @ Ho_w + Ho_b)
    sgemm_k<128, 2><<<dim3(gN, 1), 256>>>(hpre, Ho_w, 128, Ho_b, x, ln1h_g, ln1h_b, h1, 128, NN);
    // mlp = relu(h1 @ W1 + b1)
    sgemm_k<128, 1><<<dim3(gN, 2), 256>>>(h1, W1, 256, b1, nullptr, nullptr, nullptr, mlp, 256, NN);
    // out_h = LN2h(h1 + mlp @ W2 + b2)
    sgemm_k<256, 2><<<dim3(gN, 1), 256>>>(mlp, W2, 128, b2, h1, ln2h_g, ln2h_b, out_h, 128, NN);
    // out_e = LN1e(conn + ce @ Eo_w + Eo_b)
    sgemm_k<128, 2><<<dim3(gE, 1), 256>>>(ce, Eo_w, 128, Eo_b, conn, ln1e_g, ln1e_b, out_e, 128, EE);
}

// round 2
// speedup vs baseline: 1.7595x; 1.7595x over previous
#include <cuda_runtime.h>
#include <cstdint>

#define NN 50000
#define EE 600000
#define HIDD 128
#define NH 8
#define DDIM 16

// ---------------- scratch (device globals; no allocation allowed) ----------------
__device__ float g_Qh[(size_t)NN * HIDD];
__device__ float g_Kh[(size_t)NN * HIDD];
__device__ float g_Vh[(size_t)NN * HIDD];
__device__ float g_Eh[(size_t)EE * 256];   // [Ew | Eb] per edge
__device__ float g_ce[(size_t)EE * HIDD];  // conn_e / e_attn
__device__ float g_ssum[(size_t)NN * NH];
__device__ float g_agg[(size_t)NN * HIDD];
__device__ float g_row[(size_t)NN * HIDD];
__device__ float g_hpre[(size_t)NN * HIDD];
__device__ float g_h1[(size_t)NN * HIDD];
__device__ float g_mlp[(size_t)NN * 256];

__device__ __forceinline__ float to_tf32(float x) {
    float r;
    asm("cvt.rna.tf32.f32 %0, %1;" : "=f"(r) : "f"(x));
    return r;
}

__device__ __forceinline__ void mma8(float* c, const uint32_t* a, const uint32_t* b) {
    asm volatile(
        "mma.sync.aligned.m16n8k8.row.col.f32.tf32.tf32.f32 "
        "{%0,%1,%2,%3},{%4,%5,%6,%7},{%8,%9},{%0,%1,%2,%3};"
        : "+f"(c[0]), "+f"(c[1]), "+f"(c[2]), "+f"(c[3])
        : "r"(a[0]), "r"(a[1]), "r"(a[2]), "r"(a[3]), "r"(b[0]), "r"(b[1]));
}

// ---------------- TF32 tensor-core GEMM: C tile 128x128 = A[M,KD] @ W[KD,ldw] ----------------
// 8 warps, warp tile 16(m) x 128(n): each output row lives in one 4-lane group.
// EPI 0: C = acc (+bias)          EPI 1: C = relu(acc + bias)
// EPI 2: C = LN(resid + acc + bias)*g + b  (grid.y==1, ldc==128)
#define SMS 136
template <int KD, int EPI>
__global__ void __launch_bounds__(256) tgemm(
    const float* __restrict__ A, const float* __restrict__ W, int ldw,
    const float* __restrict__ bias, const float* __restrict__ resid,
    const float* __restrict__ lng, const float* __restrict__ lnb,
    float* __restrict__ C, int ldc, int M)
{
    __shared__ float As[16][SMS];
    __shared__ float Ws[16][SMS];

    const int t = threadIdx.x;
    const int lane = t & 31;
    const int wid = t >> 5;
    const int m0b = blockIdx.x * 128;
    const int n0 = blockIdx.y * 128;
    const int wm0 = wid * 16;          // warp's m offset in tile
    const int gr = lane >> 2;          // fragment group row 0..7
    const int kq = lane & 3;           // fragment k/col sub-index 0..3

    float acc[16][4];
#pragma unroll
    for (int i = 0; i < 16; i++) { acc[i][0] = acc[i][1] = acc[i][2] = acc[i][3] = 0.f; }

    const int arow = t >> 2;           // 0..63
    const int acol = (t & 3) * 4;
    const int wrow = t >> 5;           // 0..7
    const int wcol = (t & 31) * 4;

    for (int kt = 0; kt < KD; kt += 16) {
#pragma unroll
        for (int p = 0; p < 2; p++) {
            int r = arow + p * 64;
            float4 v = make_float4(0.f, 0.f, 0.f, 0.f);
            if (m0b + r < M) v = *(const float4*)&A[(size_t)(m0b + r) * KD + kt + acol];
            As[acol + 0][r] = to_tf32(v.x); As[acol + 1][r] = to_tf32(v.y);
            As[acol + 2][r] = to_tf32(v.z); As[acol + 3][r] = to_tf32(v.w);
        }
#pragma unroll
        for (int p = 0; p < 2; p++) {
            int kr = wrow + p * 8;
            float4 v = *(const float4*)&W[(size_t)(kt + kr) * ldw + n0 + wcol];
            Ws[kr][wcol + 0] = to_tf32(v.x); Ws[kr][wcol + 1] = to_tf32(v.y);
            Ws[kr][wcol + 2] = to_tf32(v.z); Ws[kr][wcol + 3] = to_tf32(v.w);
        }
        __syncthreads();
#pragma unroll
        for (int ks = 0; ks < 16; ks += 8) {
            uint32_t a[4];
            a[0] = __float_as_uint(As[ks + kq][wm0 + gr]);
            a[1] = __float_as_uint(As[ks + kq][wm0 + 8 + gr]);
            a[2] = __float_as_uint(As[ks + 4 + kq][wm0 + gr]);
            a[3] = __float_as_uint(As[ks + 4 + kq][wm0 + 8 + gr]);
#pragma unroll
            for (int nf = 0; nf < 16; nf++) {
                uint32_t b[2];
                b[0] = __float_as_uint(Ws[ks + kq][nf * 8 + gr]);
                b[1] = __float_as_uint(Ws[ks + 4 + kq][nf * 8 + gr]);
                mma8(acc[nf], a, b);
            }
        }
        __syncthreads();
    }

    if (EPI == 0 || EPI == 1) {
#pragma unroll
        for (int half = 0; half < 2; half++) {
            int r = m0b + wm0 + gr + half * 8;
            if (r >= M) continue;
#pragma unroll
            for (int nf = 0; nf < 16; nf++) {
                int c = n0 + nf * 8 + 2 * kq;
                float v0 = acc[nf][half * 2 + 0];
                float v1 = acc[nf][half * 2 + 1];
                if (bias) { v0 += bias[c]; v1 += bias[c + 1]; }
                if (EPI == 1) { v0 = fmaxf(v0, 0.f); v1 = fmaxf(v1, 0.f); }
                *(float2*)&C[(size_t)r * ldc + c] = make_float2(v0, v1);
            }
        }
    } else {
        // LayerNorm epilogue: a row's 128 cols are held by the 4 lanes of one group.
        float v[32];
#pragma unroll
        for (int half = 0; half < 2; half++) {
            int r = m0b + wm0 + gr + half * 8;
            bool ok = (r < M);
            float s = 0.f, s2 = 0.f;
#pragma unroll
            for (int nf = 0; nf < 16; nf++) {
                int c = nf * 8 + 2 * kq;
                float x0 = acc[nf][half * 2 + 0] + bias[c];
                float x1 = acc[nf][half * 2 + 1] + bias[c + 1];
                if (ok) {
                    float2 rr = *(const float2*)&resid[(size_t)r * 128 + c];
                    x0 += rr.x; x1 += rr.y;
                }
                v[2 * nf] = x0; v[2 * nf + 1] = x1;
                s += x0 + x1;
                s2 += x0 * x0 + x1 * x1;
            }
#pragma unroll
            for (int off = 1; off < 4; off <<= 1) {
                s += __shfl_xor_sync(0xffffffffu, s, off);
                s2 += __shfl_xor_sync(0xffffffffu, s2, off);
            }
            float mean = s * (1.f / 128.f);
            float var = s2 * (1.f / 128.f) - mean * mean;
            float rstd = rsqrtf(var + 1e-5f);
            if (ok) {
#pragma unroll
                for (int nf = 0; nf < 16; nf++) {
                    int c = nf * 8 + 2 * kq;
                    float o0 = (v[2 * nf] - mean) * rstd * lng[c] + lnb[c];
                    float o1 = (v[2 * nf + 1] - mean) * rstd * lng[c + 1] + lnb[c + 1];
                    *(float2*)&C[(size_t)r * 128 + c] = make_float2(o0, o1);
                }
            }
        }
    }
}

// ---------------- edge pass: conn_e, scores, segment accumulation ----------------
// one warp per edge. Softmax max-shift dropped (scores clipped to +-5 -> exact).
__global__ void __launch_bounds__(256) edge_kernel(const int* __restrict__ ei,
                                                   const float* __restrict__ Aw)
{
    int e = (int)((blockIdx.x * (size_t)blockDim.x + threadIdx.x) >> 5);
    int l = threadIdx.x & 31;
    if (e >= EE) return;
    int dst = ei[e];
    int src = ei[EE + e];
    int c0 = l * 4;
    int h = l >> 2;
    int dbase = (l & 3) * 4;

    float4 q = *(const float4*)&g_Qh[(size_t)dst * HIDD + c0];
    float4 kk = *(const float4*)&g_Kh[(size_t)src * HIDD + c0];
    float4 ew = *(const float4*)&g_Eh[(size_t)e * 256 + c0];
    float4 eb = *(const float4*)&g_Eh[(size_t)e * 256 + 128 + c0];
    float4 vv = *(const float4*)&g_Vh[(size_t)src * HIDD + c0];

    const float* qf = (const float*)&q;
    const float* kf = (const float*)&kk;
    const float* ewf = (const float*)&ew;
    const float* ebf = (const float*)&eb;
    const float* vf = (const float*)&vv;

    float ce[4];
    float part = 0.f;
#pragma unroll
    for (int i = 0; i < 4; i++) {
        float m = qf[i] + kf[i];
        float cc = m * ewf[i];
        float ss = sqrtf(fabsf(cc));
        ss = (cc >= 0.f) ? ss : -ss;          // signed sqrt
        float val = ss + ebf[i];
        ce[i] = fmaxf(val, 0.f);
        part += ce[i] * Aw[(dbase + i) * NH + h];
    }
    *(float4*)&g_ce[(size_t)e * HIDD + c0] = make_float4(ce[0], ce[1], ce[2], ce[3]);

    part += __shfl_xor_sync(0xffffffffu, part, 1);
    part += __shfl_xor_sync(0xffffffffu, part, 2);
    float s = fminf(fmaxf(part, -5.f), 5.f);
    float p = __expf(s);

    if ((l & 3) == 0) atomicAdd(&g_ssum[(size_t)dst * NH + h], p);
    float4 av = make_float4(vf[0] * p, vf[1] * p, vf[2] * p, vf[3] * p);
    float4 rv = make_float4(ce[0] * p, ce[1] * p, ce[2] * p, ce[3] * p);
    atomicAdd((float4*)&g_agg[(size_t)dst * HIDD + c0], av);
    atomicAdd((float4*)&g_row[(size_t)dst * HIDD + c0], rv);
}

// ---------------- node pass: normalize, rowV = row @ Bw, deg scaling ----------------
__global__ void __launch_bounds__(256) node_kernel(const float* __restrict__ Bw,
                                                   const float* __restrict__ deg_coef,
                                                   const float* __restrict__ log_deg)
{
    __shared__ float rbuf[8][HIDD];
    int n = (int)((blockIdx.x * (size_t)blockDim.x + threadIdx.x) >> 5);
    int wl = (threadIdx.x >> 5) & 7;
    int l = threadIdx.x & 31;
    if (n >= NN) return;
    int h = l >> 2;
    int c0 = l * 4;

    float rs = 1.f / (g_ssum[(size_t)n * NH + h] + 1e-16f);
    float4 a = *(const float4*)&g_agg[(size_t)n * HIDD + c0];
    float4 r = *(const float4*)&g_row[(size_t)n * HIDD + c0];
    a.x *= rs; a.y *= rs; a.z *= rs; a.w *= rs;
    r.x *= rs; r.y *= rs; r.z *= rs; r.w *= rs;
    *(float4*)&rbuf[wl][c0] = r;
    __syncwarp();

    float4 q = *(const float4*)&g_Qh[(size_t)n * HIDD + c0];
    const float* af = (const float*)&a;
    const float* qf = (const float*)&q;
    float ld = log_deg[n];

    float out[4];
#pragma unroll
    for (int i = 0; i < 4; i++) {
        int c = c0 + i;
        float rv = 0.f;
#pragma unroll
        for (int d = 0; d < DDIM; d++)
            rv = fmaf(rbuf[wl][h * DDIM + d], __ldg(&Bw[d * HIDD + c]), rv);
        float ha = qf[i] + af[i] + rv;
        out[i] = ha * (deg_coef[2 * c] + ld * deg_coef[2 * c + 1]);
    }
    *(float4*)&g_hpre[(size_t)n * HIDD + c0] = make_float4(out[0], out[1], out[2], out[3]);
}

// ---------------- launch ----------------
extern "C" void kernel_launch(void* const* d_in, const int* in_sizes, int n_in,
                              void* d_out, int out_size)
{
    const float* x        = (const float*)d_in[0];
    const float* conn     = (const float*)d_in[1];
    const float* log_deg  = (const float*)d_in[2];
    const int*   ei       = (const int*)d_in[3];
    const float* WQ       = (const float*)d_in[4];
    const float* WK       = (const float*)d_in[5];
    const float* WV       = (const float*)d_in[6];
    const float* WE       = (const float*)d_in[7];
    const float* Aw       = (const float*)d_in[8];
    const float* Bw       = (const float*)d_in[9];
    const float* Ho_w     = (const float*)d_in[10];
    const float* Ho_b     = (const float*)d_in[11];
    const float* Eo_w     = (const float*)d_in[12];
    const float* Eo_b     = (const float*)d_in[13];
    const float* deg_coef = (const float*)d_in[14];
    const float* ln1h_g   = (const float*)d_in[15];
    const float* ln1h_b   = (const float*)d_in[16];
    const float* ln1e_g   = (const float*)d_in[17];
    const float* ln1e_b   = (const float*)d_in[18];
    const float* ln2h_g   = (const float*)d_in[19];
    const float* ln2h_b   = (const float*)d_in[20];
    const float* W1       = (const float*)d_in[21];
    const float* b1       = (const float*)d_in[22];
    const float* W2       = (const float*)d_in[23];
    const float* b2       = (const float*)d_in[24];

    float* out_h = (float*)d_out;
    float* out_e = out_h + (size_t)NN * HIDD;

    float *Qh, *Kh, *Vh, *Eh, *ce, *ssum, *agg, *row, *hpre, *h1, *mlp;
    cudaGetSymbolAddress((void**)&Qh, g_Qh);
    cudaGetSymbolAddress((void**)&Kh, g_Kh);
    cudaGetSymbolAddress((void**)&Vh, g_Vh);
    cudaGetSymbolAddress((void**)&Eh, g_Eh);
    cudaGetSymbolAddress((void**)&ce, g_ce);
    cudaGetSymbolAddress((void**)&ssum, g_ssum);
    cudaGetSymbolAddress((void**)&agg, g_agg);
    cudaGetSymbolAddress((void**)&row, g_row);
    cudaGetSymbolAddress((void**)&hpre, g_hpre);
    cudaGetSymbolAddress((void**)&h1, g_h1);
    cudaGetSymbolAddress((void**)&mlp, g_mlp);

    const int gN = (NN + 127) / 128;   // 391
    const int gE = (EE + 127) / 128;   // 4688

    cudaMemsetAsync(ssum, 0, (size_t)NN * NH * sizeof(float), 0);
    cudaMemsetAsync(agg, 0, (size_t)NN * HIDD * sizeof(float), 0);
    cudaMemsetAsync(row, 0, (size_t)NN * HIDD * sizeof(float), 0);

    // Qh, Kh, Vh
    tgemm<128, 0><<<dim3(gN, 1), 256>>>(x, WQ, 128, nullptr, nullptr, nullptr, nullptr, Qh, 128, NN);
    tgemm<128, 0><<<dim3(gN, 1), 256>>>(x, WK, 128, nullptr, nullptr, nullptr, nullptr, Kh, 128, NN);
    tgemm<128, 0><<<dim3(gN, 1), 256>>>(x, WV, 128, nullptr, nullptr, nullptr, nullptr, Vh, 128, NN);
    // Eh = conn @ WE  [E,256]
    tgemm<128, 0><<<dim3(gE, 2), 256>>>(conn, WE, 256, nullptr, nullptr, nullptr, nullptr, Eh, 256, EE);

    // edge pass (conn_e + softmax-weighted segment sums)
    edge_kernel<<<(EE * 32 + 255) / 256, 256>>>(ei, Aw);
    // node pass -> h_pre
    node_kernel<<<(NN * 32 + 255) / 256, 256>>>(Bw, deg_coef, log_deg);

    // h1 = LN1h(x + hpre @ Ho_w + Ho_b)
    tgemm<128, 2><<<dim3(gN, 1), 256>>>(hpre, Ho_w, 128, Ho_b, x, ln1h_g, ln1h_b, h1, 128, NN);
    // mlp = relu(h1 @ W1 + b1)
    tgemm<128, 1><<<dim3(gN, 2), 256>>>(h1, W1, 256, b1, nullptr, nullptr, nullptr, mlp, 256, NN);
    // out_h = LN2h(h1 + mlp @ W2 + b2)
    tgemm<256, 2><<<dim3(gN, 1), 256>>>(mlp, W2, 128, b2, h1, ln2h_g, ln2h_b, out_h, 128, NN);
    // out_e = LN1e(conn + ce @ Eo_w + Eo_b)
    tgemm<128, 2><<<dim3(gE, 1), 256>>>(ce, Eo_w, 128, Eo_b, conn, ln1e_g, ln1e_b, out_e, 128, EE);
}